// round 12
// baseline (speedup 1.0000x reference)
#include <cuda_runtime.h>
#include <cuda_bf16.h>
#include <cstdint>
#include <math.h>

#define NN 100000
#define EE 1000000
#define BM 64
#define THREADS 1024
#define NBLK ((NN + BM - 1) / BM)      // 1563
#define GRID_PERSIST 148

#define BP 144
#define XP 272

// smem byte offsets
#define SM_B_HI   0
#define SM_B_LO   73728
#define SM_XHI    147456
#define SM_XLO    182272
#define SM_ROWSUM 217088               // float[2][64]
#define SM_CTR    217600               // int[2]
#define SM_TOTAL  217728

typedef unsigned int u32;
typedef unsigned long long u64;

// Scratch
__device__ int  g_cnt[NN];
__device__ int  g_off[NN];
__device__ int  g_cur[NN];
__device__ int  g_total;
__device__ int2 g_meta[EE];
__device__ __align__(16) __nv_bfloat16 g_Bhi[256 * BP];
__device__ __align__(16) __nv_bfloat16 g_Blo[256 * BP];

// ---------------------------------------------------------------------------
// CSR build (hist also performs the B prep so the fused kernel is launch #5)
// ---------------------------------------------------------------------------
__global__ void hist_prep_kernel(const int* __restrict__ dst,
                                 int* __restrict__ cnt,
                                 const float* __restrict__ W1,
                                 const float* __restrict__ W2,
                                 __nv_bfloat16* __restrict__ bhi,
                                 __nv_bfloat16* __restrict__ blo)
{
    int e = blockIdx.x * blockDim.x + threadIdx.x;
    if (e < EE) atomicAdd(&cnt[__ldg(dst + e)], 1);
    if (e < 256 * 128) {
        int k = e >> 7;
        int n = e & 127;
        float v = (k < 128) ? __ldg(W1 + k * 128 + n) : __ldg(W2 + (k - 128) * 128 + n);
        __nv_bfloat16 h = __float2bfloat16(v);
        bhi[k * BP + n] = h;
        blo[k * BP + n] = __float2bfloat16(v - __bfloat162float(h));
    }
}

__global__ void alloc_kernel(const int* __restrict__ cnt,
                             int* __restrict__ off,
                             int* __restrict__ cur,
                             int* __restrict__ total)
{
    int i = blockIdx.x * blockDim.x + threadIdx.x;
    if (i < NN) {
        int o = atomicAdd(total, cnt[i]);
        off[i] = o;
        cur[i] = o;
    }
}

__global__ void scatter_kernel(const int* __restrict__ src,
                               const int* __restrict__ dst,
                               const float* __restrict__ norm,
                               int* __restrict__ cur,
                               int2* __restrict__ meta)
{
    int e = blockIdx.x * blockDim.x + threadIdx.x;
    if (e >= EE) return;
    int s = __ldg(src + e);
    int d = __ldg(dst + e);
    float w = __ldg(norm + s) * __ldg(norm + d);
    int pos = atomicAdd(&cur[d], 1);
    meta[pos] = make_int2(s, __float_as_int(w));
}

// ---------------------------------------------------------------------------
// PTX helpers
// ---------------------------------------------------------------------------
__device__ __forceinline__ u32 smem_u32_of(const void* p)
{
    u32 a;
    asm("{ .reg .u64 t; cvta.to.shared.u64 t, %1; cvt.u32.u64 %0, t; }"
        : "=r"(a) : "l"(p));
    return a;
}
__device__ __forceinline__ void cp_async16(u32 dst, const void* src)
{
    asm volatile("cp.async.cg.shared.global [%0], [%1], 16;"
                 :: "r"(dst), "l"(src) : "memory");
}
__device__ __forceinline__ void ldsm_x4(u32& r0, u32& r1, u32& r2, u32& r3, u32 addr)
{
    asm volatile("ldmatrix.sync.aligned.m8n8.x4.shared.b16 {%0,%1,%2,%3}, [%4];"
                 : "=r"(r0), "=r"(r1), "=r"(r2), "=r"(r3) : "r"(addr));
}
__device__ __forceinline__ void ldsm_x4_t(u32& r0, u32& r1, u32& r2, u32& r3, u32 addr)
{
    asm volatile("ldmatrix.sync.aligned.m8n8.x4.trans.shared.b16 {%0,%1,%2,%3}, [%4];"
                 : "=r"(r0), "=r"(r1), "=r"(r2), "=r"(r3) : "r"(addr));
}
__device__ __forceinline__ void mma16816(float* c, u32 a0, u32 a1, u32 a2, u32 a3,
                                         u32 b0, u32 b1)
{
    asm volatile(
        "mma.sync.aligned.m16n8k16.row.col.f32.bf16.bf16.f32 "
        "{%0,%1,%2,%3}, {%4,%5,%6,%7}, {%8,%9}, {%0,%1,%2,%3};"
        : "+f"(c[0]), "+f"(c[1]), "+f"(c[2]), "+f"(c[3])
        : "r"(a0), "r"(a1), "r"(a2), "r"(a3), "r"(b0), "r"(b1));
}
// packed f32x2 helpers
__device__ __forceinline__ u64 dupf(float x)
{
    u64 r; u32 xi = __float_as_uint(x);
    asm("mov.b64 %0, {%1, %1};" : "=l"(r) : "r"(xi));
    return r;
}
__device__ __forceinline__ u64 mul2(u64 a, u64 b)
{
    u64 r; asm("mul.rn.f32x2 %0, %1, %2;" : "=l"(r) : "l"(a), "l"(b)); return r;
}
__device__ __forceinline__ u64 add2(u64 a, u64 b)
{
    u64 r; asm("add.rn.f32x2 %0, %1, %2;" : "=l"(r) : "l"(a), "l"(b)); return r;
}
__device__ __forceinline__ void fma2(u64& acc, u64 a, u64 b)
{
    asm("fma.rn.f32x2 %0, %1, %2, %0;" : "+l"(acc) : "l"(a), "l"(b));
}
__device__ __forceinline__ void unpack2(u64 v, float& lo, float& hi)
{
    u32 l, h;
    asm("mov.b64 {%0, %1}, %2;" : "=r"(l), "=r"(h) : "l"(v));
    lo = __uint_as_float(l);
    hi = __uint_as_float(h);
}
__device__ __forceinline__ u32 pack_hi(float x, float y)
{
    unsigned short b0 = __bfloat16_as_ushort(__float2bfloat16(x));
    unsigned short b1 = __bfloat16_as_ushort(__float2bfloat16(y));
    return (u32)b0 | ((u32)b1 << 16);
}
__device__ __forceinline__ u32 pack_lo(float x, float y)
{
    float hx = __bfloat162float(__float2bfloat16(x));
    float hy = __bfloat162float(__float2bfloat16(y));
    unsigned short b0 = __bfloat16_as_ushort(__float2bfloat16(x - hx));
    unsigned short b1 = __bfloat16_as_ushort(__float2bfloat16(y - hy));
    return (u32)b0 | ((u32)b1 << 16);
}

// ---------------------------------------------------------------------------
// Persistent fused kernel: packed-f32x2 aggregate with gather lookahead,
// work-stealing, 2 barriers/tile, mma.sync split-2 GEMM
// ---------------------------------------------------------------------------
__global__ void __launch_bounds__(THREADS, 1)
fused_kernel(const ulonglong2* __restrict__ egoq,
             const int*   __restrict__ off,
             const int*   __restrict__ cnt,
             const int2*  __restrict__ meta,
             float*       __restrict__ out)
{
    extern __shared__ char smem[];
    const u32 smem_base = smem_u32_of(smem);
    float* rowsum = (float*)(smem + SM_ROWSUM);   // [2][64]
    int*   ctr    = (int*)(smem + SM_CTR);        // [2]

    const int tid  = threadIdx.x;
    const int lane = tid & 31;
    const int warp = tid >> 5;

    // ---- 0) one-time: load Bhi/Blo into smem
    {
        const char* shi = (const char*)g_Bhi;
        const char* slo = (const char*)g_Blo;
        #pragma unroll
        for (int i = 0; i < 5; ++i) {
            int m = tid + i * THREADS;
            if (m < 4608) {
                cp_async16(smem_base + SM_B_HI + m * 16, shi + m * 16);
                cp_async16(smem_base + SM_B_LO + m * 16, slo + m * 16);
            }
        }
        asm volatile("cp.async.commit_group;" ::: "memory");
        asm volatile("cp.async.wait_group 0;" ::: "memory");
    }
    if (tid < 2 * BM) rowsum[tid] = 0.f;
    if (tid < 2) ctr[tid] = 0;
    __syncthreads();

    // GEMM constants: warp grid 4m x 8n; warp tile 16m x 16n
    const int m0 = (warp >> 3) * 16;
    const int n0 = (warp & 7) * 16;
    const u32 a_row = m0 + (lane & 15);
    const u32 a_col = (lane >> 4) * 8;
    const u32 aHiBase = smem_base + SM_XHI + a_row * (XP * 2) + a_col * 2;
    const u32 aLoBase = smem_base + SM_XLO + a_row * (XP * 2) + a_col * 2;
    const u32 b_krow = (lane & 7) + ((lane >> 3) & 1) * 8;
    const u32 b_ncol = (lane >> 4) * 8;
    const u32 bHiBase = smem_base + SM_B_HI + b_krow * (BP * 2) + (n0 + b_ncol) * 2;
    const u32 bLoBase = smem_base + SM_B_LO + b_krow * (BP * 2) + (n0 + b_ncol) * 2;
    const int r0 = m0 + (lane >> 2);
    const int r1 = r0 + 8;

    int par = 0;
    for (int tile = blockIdx.x; tile < NBLK; tile += GRID_PERSIST, par ^= 1) {
        const int rowBase = tile * BM;

        // ---- 1) aggregate (packed f32x2, gather lookahead): steal nodes
        for (;;) {
            int r;
            if (lane == 0) r = atomicAdd(&ctr[par], 1);
            r = __shfl_sync(0xffffffffu, r, 0);
            if (r >= BM) break;

            int node = rowBase + r;
            bool valid = node < NN;

            ulonglong2 hd2 = valid ? __ldg(egoq + (size_t)node * 32 + lane)
                                   : make_ulonglong2(0ull, 0ull);
            u64 aP0 = hd2.x, aP1 = hd2.y;     // self term
            u64 bP0 = 0ull,  bP1 = 0ull;

            int n  = valid ? __ldg(cnt + node) : 0;
            int e0 = valid ? __ldg(off + node) : 0;

            for (int c = 0; c < n; c += 32) {
                int lim = min(32, n - c);
                int2 mm = (lane < lim) ? __ldg(meta + e0 + c + lane)
                                       : make_int2(0, 0);
                int nb = lim & ~3;
                ulonglong2 h[4];
                if (nb) {
                    #pragma unroll
                    for (int t = 0; t < 4; ++t) {
                        int s = __shfl_sync(0xffffffffu, mm.x, t);
                        h[t] = __ldg(egoq + (size_t)s * 32 + lane);
                    }
                }
                for (int j = 0; j < nb; j += 4) {
                    u64 w0 = dupf(__int_as_float(__shfl_sync(0xffffffffu, mm.y, j + 0)));
                    u64 w1 = dupf(__int_as_float(__shfl_sync(0xffffffffu, mm.y, j + 1)));
                    u64 w2 = dupf(__int_as_float(__shfl_sync(0xffffffffu, mm.y, j + 2)));
                    u64 w3 = dupf(__int_as_float(__shfl_sync(0xffffffffu, mm.y, j + 3)));
                    ulonglong2 c0 = h[0], c1 = h[1], c2 = h[2], c3 = h[3];
                    if (j + 4 < nb) {
                        #pragma unroll
                        for (int t = 0; t < 4; ++t) {
                            int s = __shfl_sync(0xffffffffu, mm.x, j + 4 + t);
                            h[t] = __ldg(egoq + (size_t)s * 32 + lane);
                        }
                    }
                    u64 t;
                    t = mul2(w0, c0.x); aP0 = add2(aP0, t); fma2(bP0, t, hd2.x);
                    t = mul2(w0, c0.y); aP1 = add2(aP1, t); fma2(bP1, t, hd2.y);
                    t = mul2(w1, c1.x); aP0 = add2(aP0, t); fma2(bP0, t, hd2.x);
                    t = mul2(w1, c1.y); aP1 = add2(aP1, t); fma2(bP1, t, hd2.y);
                    t = mul2(w2, c2.x); aP0 = add2(aP0, t); fma2(bP0, t, hd2.x);
                    t = mul2(w2, c2.y); aP1 = add2(aP1, t); fma2(bP1, t, hd2.y);
                    t = mul2(w3, c3.x); aP0 = add2(aP0, t); fma2(bP0, t, hd2.x);
                    t = mul2(w3, c3.y); aP1 = add2(aP1, t); fma2(bP1, t, hd2.y);
                }
                for (int j = nb; j < lim; ++j) {
                    int   s0 = __shfl_sync(0xffffffffu, mm.x, j);
                    u64   w0 = dupf(__int_as_float(__shfl_sync(0xffffffffu, mm.y, j)));
                    ulonglong2 h0 = __ldg(egoq + (size_t)s0 * 32 + lane);
                    u64 t;
                    t = mul2(w0, h0.x); aP0 = add2(aP0, t); fma2(bP0, t, hd2.x);
                    t = mul2(w0, h0.y); aP1 = add2(aP1, t); fma2(bP1, t, hd2.y);
                }
            }

            float ax, ay, az, aw, bx, by, bz, bw;
            unpack2(aP0, ax, ay); unpack2(aP1, az, aw);
            unpack2(bP0, bx, by); unpack2(bP1, bz, bw);

            u32* xh = (u32*)(smem + SM_XHI + (size_t)r * (XP * 2));
            u32* xl = (u32*)(smem + SM_XLO + (size_t)r * (XP * 2));
            xh[lane * 2 + 0]  = pack_hi(ax, ay);
            xh[lane * 2 + 1]  = pack_hi(az, aw);
            xh[64 + lane * 2] = pack_hi(bx, by);
            xh[65 + lane * 2] = pack_hi(bz, bw);
            xl[lane * 2 + 0]  = pack_lo(ax, ay);
            xl[lane * 2 + 1]  = pack_lo(az, aw);
            xl[64 + lane * 2] = pack_lo(bx, by);
            xl[65 + lane * 2] = pack_lo(bz, bw);
        }
        __syncthreads();                 // bar1: X complete

        if (tid == 0) ctr[par ^ 1] = 0;
        if (tid < BM) rowsum[(par ^ 1) * BM + tid] = 0.f;

        // ---- 2) GEMM: warp tile 16m x 16n; K=256, split-2
        float acc[2][4];
        #pragma unroll
        for (int i = 0; i < 2; ++i)
            #pragma unroll
            for (int j = 0; j < 4; ++j) acc[i][j] = 0.f;

        #pragma unroll 4
        for (int ks = 0; ks < 16; ++ks) {
            const u32 kOffA = ks * 32;
            const u32 kOffB = ks * 16 * (BP * 2);
            u32 ah0, ah1, ah2, ah3, al0, al1, al2, al3;
            ldsm_x4(ah0, ah1, ah2, ah3, aHiBase + kOffA);
            ldsm_x4(al0, al1, al2, al3, aLoBase + kOffA);

            u32 bh0, bh1, bh2, bh3, bl0, bl1, bl2, bl3;
            ldsm_x4_t(bh0, bh1, bh2, bh3, bHiBase + kOffB);
            ldsm_x4_t(bl0, bl1, bl2, bl3, bLoBase + kOffB);
            mma16816(acc[0], ah0, ah1, ah2, ah3, bh0, bh1);
            mma16816(acc[0], ah0, ah1, ah2, ah3, bl0, bl1);
            mma16816(acc[0], al0, al1, al2, al3, bh0, bh1);
            mma16816(acc[1], ah0, ah1, ah2, ah3, bh2, bh3);
            mma16816(acc[1], ah0, ah1, ah2, ah3, bl2, bl3);
            mma16816(acc[1], al0, al1, al2, al3, bh2, bh3);
        }

        // ---- 3) leaky relu + per-row sumsq partials
        float p0 = 0.f, p1 = 0.f;
        #pragma unroll
        for (int nt = 0; nt < 2; ++nt) {
            #pragma unroll
            for (int j = 0; j < 4; ++j) {
                float v = acc[nt][j];
                v = (v >= 0.f) ? v : 0.2f * v;
                acc[nt][j] = v;
                if (j < 2) p0 = fmaf(v, v, p0);
                else       p1 = fmaf(v, v, p1);
            }
        }
        p0 += __shfl_xor_sync(0xffffffffu, p0, 1);
        p0 += __shfl_xor_sync(0xffffffffu, p0, 2);
        p1 += __shfl_xor_sync(0xffffffffu, p1, 1);
        p1 += __shfl_xor_sync(0xffffffffu, p1, 2);
        if ((lane & 3) == 0) {
            atomicAdd(rowsum + par * BM + r0, p0);
            atomicAdd(rowsum + par * BM + r1, p1);
        }
        __syncthreads();                 // bar2: rowsum complete, X reads done

        // ---- 4) scale + store
        const float inv0 = 1.0f / fmaxf(sqrtf(rowsum[par * BM + r0]), 1e-12f);
        const float inv1 = 1.0f / fmaxf(sqrtf(rowsum[par * BM + r1]), 1e-12f);
        float2* out2 = (float2*)out;
        const int g0 = rowBase + r0;
        const int g1 = rowBase + r1;
        const int colh = (n0 + (lane & 3) * 2) >> 1;
        #pragma unroll
        for (int nt = 0; nt < 2; ++nt) {
            int c2 = colh + nt * 4;
            if (g0 < NN)
                out2[(size_t)g0 * 64 + c2] = make_float2(acc[nt][0] * inv0, acc[nt][1] * inv0);
            if (g1 < NN)
                out2[(size_t)g1 * 64 + c2] = make_float2(acc[nt][2] * inv1, acc[nt][3] * inv1);
        }
    }
}

// ---------------------------------------------------------------------------
// Launch
// ---------------------------------------------------------------------------
extern "C" void kernel_launch(void* const* d_in, const int* in_sizes, int n_in,
                              void* d_out, int out_size)
{
    const float* ego  = (const float*)d_in[0];
    const float* norm = (const float*)d_in[1];
    const int*   src  = (const int*)d_in[2];
    const int*   dst  = (const int*)d_in[3];
    const float* W1   = (const float*)d_in[4];
    const float* W2   = (const float*)d_in[5];
    float* out = (float*)d_out;

    int*  cnt;   cudaGetSymbolAddress((void**)&cnt,   g_cnt);
    int*  off;   cudaGetSymbolAddress((void**)&off,   g_off);
    int*  cur;   cudaGetSymbolAddress((void**)&cur,   g_cur);
    int*  total; cudaGetSymbolAddress((void**)&total, g_total);
    int2* meta;  cudaGetSymbolAddress((void**)&meta,  g_meta);
    __nv_bfloat16* bhi; cudaGetSymbolAddress((void**)&bhi, g_Bhi);
    __nv_bfloat16* blo; cudaGetSymbolAddress((void**)&blo, g_Blo);

    cudaMemsetAsync(cnt, 0, NN * sizeof(int));
    cudaMemsetAsync(total, 0, sizeof(int));
    hist_prep_kernel<<<(EE + 255) / 256, 256>>>(dst, cnt, W1, W2, bhi, blo);
    alloc_kernel<<<(NN + 255) / 256, 256>>>(cnt, off, cur, total);
    scatter_kernel<<<(EE + 255) / 256, 256>>>(src, dst, norm, cur, meta);

    cudaFuncSetAttribute(fused_kernel,
                         cudaFuncAttributeMaxDynamicSharedMemorySize, SM_TOTAL);
    fused_kernel<<<GRID_PERSIST, THREADS, SM_TOTAL>>>(
        (const ulonglong2*)ego, off, cnt, meta, out);
}

// round 13
// speedup vs baseline: 1.0189x; 1.0189x over previous
#include <cuda_runtime.h>
#include <cuda_bf16.h>
#include <cstdint>
#include <math.h>

#define NN 100000
#define EE 1000000
#define BM 64
#define THREADS 1024
#define NBLK ((NN + BM - 1) / BM)      // 1563
#define GRID_PERSIST 148

#define BP 144
#define XP 272

// smem byte offsets
#define SM_B_HI   0
#define SM_B_LO   73728
#define SM_XHI    147456
#define SM_XLO    182272
#define SM_ROWSUM 217088               // float[2][64]
#define SM_CTR    217600               // int[2]
#define SM_TOTAL  217728

typedef unsigned int u32;
typedef unsigned long long u64;

// Scratch
__device__ int  g_cnt[NN];
__device__ int  g_off[NN];
__device__ int  g_cur[NN];
__device__ int  g_total;
__device__ int2 g_meta[EE];
__device__ __align__(16) __nv_bfloat16 g_Bhi[256 * BP];
__device__ __align__(16) __nv_bfloat16 g_Blo[256 * BP];

// ---------------------------------------------------------------------------
// CSR build (hist also performs the B prep so the fused kernel is launch #5)
// ---------------------------------------------------------------------------
__global__ void hist_prep_kernel(const int* __restrict__ dst,
                                 int* __restrict__ cnt,
                                 const float* __restrict__ W1,
                                 const float* __restrict__ W2,
                                 __nv_bfloat16* __restrict__ bhi,
                                 __nv_bfloat16* __restrict__ blo)
{
    int e = blockIdx.x * blockDim.x + threadIdx.x;
    if (e < EE) atomicAdd(&cnt[__ldg(dst + e)], 1);
    if (e < 256 * 128) {
        int k = e >> 7;
        int n = e & 127;
        float v = (k < 128) ? __ldg(W1 + k * 128 + n) : __ldg(W2 + (k - 128) * 128 + n);
        __nv_bfloat16 h = __float2bfloat16(v);
        bhi[k * BP + n] = h;
        blo[k * BP + n] = __float2bfloat16(v - __bfloat162float(h));
    }
}

__global__ void alloc_kernel(const int* __restrict__ cnt,
                             int* __restrict__ off,
                             int* __restrict__ cur,
                             int* __restrict__ total)
{
    int i = blockIdx.x * blockDim.x + threadIdx.x;
    if (i < NN) {
        int o = atomicAdd(total, cnt[i]);
        off[i] = o;
        cur[i] = o;
    }
}

__global__ void scatter_kernel(const int* __restrict__ src,
                               const int* __restrict__ dst,
                               const float* __restrict__ norm,
                               int* __restrict__ cur,
                               int2* __restrict__ meta)
{
    int e = blockIdx.x * blockDim.x + threadIdx.x;
    if (e >= EE) return;
    int s = __ldg(src + e);
    int d = __ldg(dst + e);
    float w = __ldg(norm + s) * __ldg(norm + d);
    int pos = atomicAdd(&cur[d], 1);
    meta[pos] = make_int2(s, __float_as_int(w));
}

// ---------------------------------------------------------------------------
// PTX helpers
// ---------------------------------------------------------------------------
__device__ __forceinline__ u32 smem_u32_of(const void* p)
{
    u32 a;
    asm("{ .reg .u64 t; cvta.to.shared.u64 t, %1; cvt.u32.u64 %0, t; }"
        : "=r"(a) : "l"(p));
    return a;
}
__device__ __forceinline__ void cp_async16(u32 dst, const void* src)
{
    asm volatile("cp.async.cg.shared.global [%0], [%1], 16;"
                 :: "r"(dst), "l"(src) : "memory");
}
__device__ __forceinline__ void ldsm_x4(u32& r0, u32& r1, u32& r2, u32& r3, u32 addr)
{
    asm volatile("ldmatrix.sync.aligned.m8n8.x4.shared.b16 {%0,%1,%2,%3}, [%4];"
                 : "=r"(r0), "=r"(r1), "=r"(r2), "=r"(r3) : "r"(addr));
}
__device__ __forceinline__ void ldsm_x4_t(u32& r0, u32& r1, u32& r2, u32& r3, u32 addr)
{
    asm volatile("ldmatrix.sync.aligned.m8n8.x4.trans.shared.b16 {%0,%1,%2,%3}, [%4];"
                 : "=r"(r0), "=r"(r1), "=r"(r2), "=r"(r3) : "r"(addr));
}
__device__ __forceinline__ void mma16816(float* c, u32 a0, u32 a1, u32 a2, u32 a3,
                                         u32 b0, u32 b1)
{
    asm volatile(
        "mma.sync.aligned.m16n8k16.row.col.f32.bf16.bf16.f32 "
        "{%0,%1,%2,%3}, {%4,%5,%6,%7}, {%8,%9}, {%0,%1,%2,%3};"
        : "+f"(c[0]), "+f"(c[1]), "+f"(c[2]), "+f"(c[3])
        : "r"(a0), "r"(a1), "r"(a2), "r"(a3), "r"(b0), "r"(b1));
}
// packed f32x2 helpers
__device__ __forceinline__ u64 dupf(float x)
{
    u64 r; u32 xi = __float_as_uint(x);
    asm("mov.b64 %0, {%1, %1};" : "=l"(r) : "r"(xi));
    return r;
}
__device__ __forceinline__ u64 mul2(u64 a, u64 b)
{
    u64 r; asm("mul.rn.f32x2 %0, %1, %2;" : "=l"(r) : "l"(a), "l"(b)); return r;
}
__device__ __forceinline__ u64 add2(u64 a, u64 b)
{
    u64 r; asm("add.rn.f32x2 %0, %1, %2;" : "=l"(r) : "l"(a), "l"(b)); return r;
}
__device__ __forceinline__ void fma2(u64& acc, u64 a, u64 b)
{
    asm("fma.rn.f32x2 %0, %1, %2, %0;" : "+l"(acc) : "l"(a), "l"(b));
}
// split a packed f32 pair into (hi bf16x2 via truncation, lo bf16x2 via rn)
__device__ __forceinline__ void split_pair(u64 v, u32& hi, u32& lo)
{
    u32 l, h;
    asm("mov.b64 {%0, %1}, %2;" : "=r"(l), "=r"(h) : "l"(v));
    // hi = {trunc_bf16(l) , trunc_bf16(h)}: take top 2 bytes of each
    asm("prmt.b32 %0, %1, %2, 0x7632;" : "=r"(hi) : "r"(l), "r"(h));
    float fl = __uint_as_float(l);
    float fh = __uint_as_float(h);
    float tl = __uint_as_float(l & 0xFFFF0000u);
    float th = __uint_as_float(h & 0xFFFF0000u);
    float rl = fl - tl;
    float rh = fh - th;
    asm("cvt.rn.bf16x2.f32 %0, %1, %2;" : "=r"(lo) : "f"(rh), "f"(rl));
}

// ---------------------------------------------------------------------------
// Persistent fused kernel: single-accumulator aggregate (B = S .* ego),
// PRMT-based hi/lo split, work-stealing, 2 barriers/tile, mma.sync GEMM
// ---------------------------------------------------------------------------
__global__ void __launch_bounds__(THREADS, 1)
fused_kernel(const ulonglong2* __restrict__ egoq,
             const int*   __restrict__ off,
             const int*   __restrict__ cnt,
             const int2*  __restrict__ meta,
             float*       __restrict__ out)
{
    extern __shared__ char smem[];
    const u32 smem_base = smem_u32_of(smem);
    float* rowsum = (float*)(smem + SM_ROWSUM);   // [2][64]
    int*   ctr    = (int*)(smem + SM_CTR);        // [2]

    const int tid  = threadIdx.x;
    const int lane = tid & 31;
    const int warp = tid >> 5;

    // ---- 0) one-time: load Bhi/Blo into smem
    {
        const char* shi = (const char*)g_Bhi;
        const char* slo = (const char*)g_Blo;
        #pragma unroll
        for (int i = 0; i < 5; ++i) {
            int m = tid + i * THREADS;
            if (m < 4608) {
                cp_async16(smem_base + SM_B_HI + m * 16, shi + m * 16);
                cp_async16(smem_base + SM_B_LO + m * 16, slo + m * 16);
            }
        }
        asm volatile("cp.async.commit_group;" ::: "memory");
        asm volatile("cp.async.wait_group 0;" ::: "memory");
    }
    if (tid < 2 * BM) rowsum[tid] = 0.f;
    if (tid < 2) ctr[tid] = 0;
    __syncthreads();

    // GEMM constants: warp grid 4m x 8n; warp tile 16m x 16n
    const int m0 = (warp >> 3) * 16;
    const int n0 = (warp & 7) * 16;
    const u32 a_row = m0 + (lane & 15);
    const u32 a_col = (lane >> 4) * 8;
    const u32 aHiBase = smem_base + SM_XHI + a_row * (XP * 2) + a_col * 2;
    const u32 aLoBase = smem_base + SM_XLO + a_row * (XP * 2) + a_col * 2;
    const u32 b_krow = (lane & 7) + ((lane >> 3) & 1) * 8;
    const u32 b_ncol = (lane >> 4) * 8;
    const u32 bHiBase = smem_base + SM_B_HI + b_krow * (BP * 2) + (n0 + b_ncol) * 2;
    const u32 bLoBase = smem_base + SM_B_LO + b_krow * (BP * 2) + (n0 + b_ncol) * 2;
    const int r0 = m0 + (lane >> 2);
    const int r1 = r0 + 8;

    int par = 0;
    for (int tile = blockIdx.x; tile < NBLK; tile += GRID_PERSIST, par ^= 1) {
        const int rowBase = tile * BM;

        // ---- 1) aggregate: S = sum(w*h_src); steal nodes until exhausted
        for (;;) {
            int r;
            if (lane == 0) r = atomicAdd(&ctr[par], 1);
            r = __shfl_sync(0xffffffffu, r, 0);
            if (r >= BM) break;

            int node = rowBase + r;
            bool valid = node < NN;

            ulonglong2 hd2 = valid ? __ldg(egoq + (size_t)node * 32 + lane)
                                   : make_ulonglong2(0ull, 0ull);
            u64 sP0 = 0ull, sP1 = 0ull;

            int n  = valid ? __ldg(cnt + node) : 0;
            int e0 = valid ? __ldg(off + node) : 0;

            for (int c = 0; c < n; c += 32) {
                int lim = min(32, n - c);
                int2 mm = (lane < lim) ? __ldg(meta + e0 + c + lane)
                                       : make_int2(0, 0);
                int nb = lim & ~3;
                ulonglong2 h[4];
                if (nb) {
                    #pragma unroll
                    for (int t = 0; t < 4; ++t) {
                        int s = __shfl_sync(0xffffffffu, mm.x, t);
                        h[t] = __ldg(egoq + (size_t)s * 32 + lane);
                    }
                }
                for (int j = 0; j < nb; j += 4) {
                    u64 w0 = dupf(__int_as_float(__shfl_sync(0xffffffffu, mm.y, j + 0)));
                    u64 w1 = dupf(__int_as_float(__shfl_sync(0xffffffffu, mm.y, j + 1)));
                    u64 w2 = dupf(__int_as_float(__shfl_sync(0xffffffffu, mm.y, j + 2)));
                    u64 w3 = dupf(__int_as_float(__shfl_sync(0xffffffffu, mm.y, j + 3)));
                    ulonglong2 c0 = h[0], c1 = h[1], c2 = h[2], c3 = h[3];
                    if (j + 4 < nb) {
                        #pragma unroll
                        for (int t = 0; t < 4; ++t) {
                            int s = __shfl_sync(0xffffffffu, mm.x, j + 4 + t);
                            h[t] = __ldg(egoq + (size_t)s * 32 + lane);
                        }
                    }
                    fma2(sP0, w0, c0.x); fma2(sP1, w0, c0.y);
                    fma2(sP0, w1, c1.x); fma2(sP1, w1, c1.y);
                    fma2(sP0, w2, c2.x); fma2(sP1, w2, c2.y);
                    fma2(sP0, w3, c3.x); fma2(sP1, w3, c3.y);
                }
                for (int j = nb; j < lim; ++j) {
                    int s0 = __shfl_sync(0xffffffffu, mm.x, j);
                    u64 w0 = dupf(__int_as_float(__shfl_sync(0xffffffffu, mm.y, j)));
                    ulonglong2 h0 = __ldg(egoq + (size_t)s0 * 32 + lane);
                    fma2(sP0, w0, h0.x); fma2(sP1, w0, h0.y);
                }
            }

            // A = ego + S ; Bpart = S .* ego
            u64 aP0 = add2(hd2.x, sP0);
            u64 aP1 = add2(hd2.y, sP1);
            u64 bP0 = mul2(sP0, hd2.x);
            u64 bP1 = mul2(sP1, hd2.y);

            u32 h0, l0, h1, l1, h2, l2, h3, l3;
            split_pair(aP0, h0, l0);
            split_pair(aP1, h1, l1);
            split_pair(bP0, h2, l2);
            split_pair(bP1, h3, l3);

            uint2* xh = (uint2*)(smem + SM_XHI + (size_t)r * (XP * 2));
            uint2* xl = (uint2*)(smem + SM_XLO + (size_t)r * (XP * 2));
            xh[lane]      = make_uint2(h0, h1);
            xh[32 + lane] = make_uint2(h2, h3);
            xl[lane]      = make_uint2(l0, l1);
            xl[32 + lane] = make_uint2(l2, l3);
        }
        __syncthreads();                 // bar1: X complete

        if (tid == 0) ctr[par ^ 1] = 0;
        if (tid < BM) rowsum[(par ^ 1) * BM + tid] = 0.f;

        // ---- 2) GEMM: warp tile 16m x 16n; K=256, split-2
        float acc[2][4];
        #pragma unroll
        for (int i = 0; i < 2; ++i)
            #pragma unroll
            for (int j = 0; j < 4; ++j) acc[i][j] = 0.f;

        #pragma unroll 4
        for (int ks = 0; ks < 16; ++ks) {
            const u32 kOffA = ks * 32;
            const u32 kOffB = ks * 16 * (BP * 2);
            u32 ah0, ah1, ah2, ah3, al0, al1, al2, al3;
            ldsm_x4(ah0, ah1, ah2, ah3, aHiBase + kOffA);
            ldsm_x4(al0, al1, al2, al3, aLoBase + kOffA);

            u32 bh0, bh1, bh2, bh3, bl0, bl1, bl2, bl3;
            ldsm_x4_t(bh0, bh1, bh2, bh3, bHiBase + kOffB);
            ldsm_x4_t(bl0, bl1, bl2, bl3, bLoBase + kOffB);
            mma16816(acc[0], ah0, ah1, ah2, ah3, bh0, bh1);
            mma16816(acc[0], ah0, ah1, ah2, ah3, bl0, bl1);
            mma16816(acc[0], al0, al1, al2, al3, bh0, bh1);
            mma16816(acc[1], ah0, ah1, ah2, ah3, bh2, bh3);
            mma16816(acc[1], ah0, ah1, ah2, ah3, bl2, bl3);
            mma16816(acc[1], al0, al1, al2, al3, bh2, bh3);
        }

        // ---- 3) leaky relu + per-row sumsq partials
        float p0 = 0.f, p1 = 0.f;
        #pragma unroll
        for (int nt = 0; nt < 2; ++nt) {
            #pragma unroll
            for (int j = 0; j < 4; ++j) {
                float v = acc[nt][j];
                v = (v >= 0.f) ? v : 0.2f * v;
                acc[nt][j] = v;
                if (j < 2) p0 = fmaf(v, v, p0);
                else       p1 = fmaf(v, v, p1);
            }
        }
        p0 += __shfl_xor_sync(0xffffffffu, p0, 1);
        p0 += __shfl_xor_sync(0xffffffffu, p0, 2);
        p1 += __shfl_xor_sync(0xffffffffu, p1, 1);
        p1 += __shfl_xor_sync(0xffffffffu, p1, 2);
        if ((lane & 3) == 0) {
            atomicAdd(rowsum + par * BM + r0, p0);
            atomicAdd(rowsum + par * BM + r1, p1);
        }
        __syncthreads();                 // bar2: rowsum complete, X reads done

        // ---- 4) scale + store
        const float inv0 = 1.0f / fmaxf(sqrtf(rowsum[par * BM + r0]), 1e-12f);
        const float inv1 = 1.0f / fmaxf(sqrtf(rowsum[par * BM + r1]), 1e-12f);
        float2* out2 = (float2*)out;
        const int g0 = rowBase + r0;
        const int g1 = rowBase + r1;
        const int colh = (n0 + (lane & 3) * 2) >> 1;
        #pragma unroll
        for (int nt = 0; nt < 2; ++nt) {
            int c2 = colh + nt * 4;
            if (g0 < NN)
                out2[(size_t)g0 * 64 + c2] = make_float2(acc[nt][0] * inv0, acc[nt][1] * inv0);
            if (g1 < NN)
                out2[(size_t)g1 * 64 + c2] = make_float2(acc[nt][2] * inv1, acc[nt][3] * inv1);
        }
    }
}

// ---------------------------------------------------------------------------
// Launch
// ---------------------------------------------------------------------------
extern "C" void kernel_launch(void* const* d_in, const int* in_sizes, int n_in,
                              void* d_out, int out_size)
{
    const float* ego  = (const float*)d_in[0];
    const float* norm = (const float*)d_in[1];
    const int*   src  = (const int*)d_in[2];
    const int*   dst  = (const int*)d_in[3];
    const float* W1   = (const float*)d_in[4];
    const float* W2   = (const float*)d_in[5];
    float* out = (float*)d_out;

    int*  cnt;   cudaGetSymbolAddress((void**)&cnt,   g_cnt);
    int*  off;   cudaGetSymbolAddress((void**)&off,   g_off);
    int*  cur;   cudaGetSymbolAddress((void**)&cur,   g_cur);
    int*  total; cudaGetSymbolAddress((void**)&total, g_total);
    int2* meta;  cudaGetSymbolAddress((void**)&meta,  g_meta);
    __nv_bfloat16* bhi; cudaGetSymbolAddress((void**)&bhi, g_Bhi);
    __nv_bfloat16* blo; cudaGetSymbolAddress((void**)&blo, g_Blo);

    cudaMemsetAsync(cnt, 0, NN * sizeof(int));
    cudaMemsetAsync(total, 0, sizeof(int));
    hist_prep_kernel<<<(EE + 255) / 256, 256>>>(dst, cnt, W1, W2, bhi, blo);
    alloc_kernel<<<(NN + 255) / 256, 256>>>(cnt, off, cur, total);
    scatter_kernel<<<(EE + 255) / 256, 256>>>(src, dst, norm, cur, meta);

    cudaFuncSetAttribute(fused_kernel,
                         cudaFuncAttributeMaxDynamicSharedMemorySize, SM_TOTAL);
    fused_kernel<<<GRID_PERSIST, THREADS, SM_TOTAL>>>(
        (const ulonglong2*)ego, off, cnt, meta, out);
}

// round 14
// speedup vs baseline: 1.3004x; 1.2763x over previous
#include <cuda_runtime.h>
#include <cuda_bf16.h>
#include <cstdint>
#include <math.h>

#define NN 100000
#define EE 1000000
#define BM 64
#define THREADS 1024
#define NBLK ((NN + BM - 1) / BM)      // 1563
#define GRID_PERSIST 148

// conflict-free strides: odd multiples of 16B
#define BP 136                          // B row: 272 B = 17*16
#define XP 264                          // X row: 528 B = 33*16

#define B_BYTES (256 * BP * 2)          // 69632
#define X_BYTES (BM * XP * 2)           // 33792

// smem byte offsets
#define SM_B_HI   0
#define SM_B_LO   (B_BYTES)                     // 69632
#define SM_XHI    (2 * B_BYTES)                 // 139264
#define SM_XLO    (2 * B_BYTES + X_BYTES)       // 173056
#define SM_ROWSUM (2 * B_BYTES + 2 * X_BYTES)   // 206848
#define SM_CTR    (SM_ROWSUM + 512)             // 207360
#define SM_TOTAL  (SM_CTR + 128)                // 207488

typedef unsigned int u32;
typedef unsigned long long u64;

// Scratch
__device__ int  g_cnt[NN];
__device__ int  g_off[NN];
__device__ int  g_cur[NN];
__device__ int  g_total;
__device__ int2 g_meta[EE];
__device__ __align__(16) __nv_bfloat16 g_Bhi[256 * BP];
__device__ __align__(16) __nv_bfloat16 g_Blo[256 * BP];

// ---------------------------------------------------------------------------
// CSR build (hist also performs the B prep so the fused kernel is launch #5)
// ---------------------------------------------------------------------------
__global__ void hist_prep_kernel(const int* __restrict__ dst,
                                 int* __restrict__ cnt,
                                 const float* __restrict__ W1,
                                 const float* __restrict__ W2,
                                 __nv_bfloat16* __restrict__ bhi,
                                 __nv_bfloat16* __restrict__ blo)
{
    int e = blockIdx.x * blockDim.x + threadIdx.x;
    if (e < EE) atomicAdd(&cnt[__ldg(dst + e)], 1);
    if (e < 256 * 128) {
        int k = e >> 7;
        int n = e & 127;
        float v = (k < 128) ? __ldg(W1 + k * 128 + n) : __ldg(W2 + (k - 128) * 128 + n);
        __nv_bfloat16 h = __float2bfloat16(v);
        bhi[k * BP + n] = h;
        blo[k * BP + n] = __float2bfloat16(v - __bfloat162float(h));
    }
}

__global__ void alloc_kernel(const int* __restrict__ cnt,
                             int* __restrict__ off,
                             int* __restrict__ cur,
                             int* __restrict__ total)
{
    int i = blockIdx.x * blockDim.x + threadIdx.x;
    if (i < NN) {
        int o = atomicAdd(total, cnt[i]);
        off[i] = o;
        cur[i] = o;
    }
}

__global__ void scatter_kernel(const int* __restrict__ src,
                               const int* __restrict__ dst,
                               const float* __restrict__ norm,
                               int* __restrict__ cur,
                               int2* __restrict__ meta)
{
    int e = blockIdx.x * blockDim.x + threadIdx.x;
    if (e >= EE) return;
    int s = __ldg(src + e);
    int d = __ldg(dst + e);
    float w = __ldg(norm + s) * __ldg(norm + d);
    int pos = atomicAdd(&cur[d], 1);
    meta[pos] = make_int2(s, __float_as_int(w));
}

// ---------------------------------------------------------------------------
// PTX helpers
// ---------------------------------------------------------------------------
__device__ __forceinline__ u32 smem_u32_of(const void* p)
{
    u32 a;
    asm("{ .reg .u64 t; cvta.to.shared.u64 t, %1; cvt.u32.u64 %0, t; }"
        : "=r"(a) : "l"(p));
    return a;
}
__device__ __forceinline__ void cp_async16(u32 dst, const void* src)
{
    asm volatile("cp.async.cg.shared.global [%0], [%1], 16;"
                 :: "r"(dst), "l"(src) : "memory");
}
__device__ __forceinline__ void ldsm_x4(u32& r0, u32& r1, u32& r2, u32& r3, u32 addr)
{
    asm volatile("ldmatrix.sync.aligned.m8n8.x4.shared.b16 {%0,%1,%2,%3}, [%4];"
                 : "=r"(r0), "=r"(r1), "=r"(r2), "=r"(r3) : "r"(addr));
}
__device__ __forceinline__ void ldsm_x4_t(u32& r0, u32& r1, u32& r2, u32& r3, u32 addr)
{
    asm volatile("ldmatrix.sync.aligned.m8n8.x4.trans.shared.b16 {%0,%1,%2,%3}, [%4];"
                 : "=r"(r0), "=r"(r1), "=r"(r2), "=r"(r3) : "r"(addr));
}
__device__ __forceinline__ void mma16816(float* c, u32 a0, u32 a1, u32 a2, u32 a3,
                                         u32 b0, u32 b1)
{
    asm volatile(
        "mma.sync.aligned.m16n8k16.row.col.f32.bf16.bf16.f32 "
        "{%0,%1,%2,%3}, {%4,%5,%6,%7}, {%8,%9}, {%0,%1,%2,%3};"
        : "+f"(c[0]), "+f"(c[1]), "+f"(c[2]), "+f"(c[3])
        : "r"(a0), "r"(a1), "r"(a2), "r"(a3), "r"(b0), "r"(b1));
}
// packed f32x2 helpers
__device__ __forceinline__ u64 dupf(float x)
{
    u64 r; u32 xi = __float_as_uint(x);
    asm("mov.b64 %0, {%1, %1};" : "=l"(r) : "r"(xi));
    return r;
}
__device__ __forceinline__ u64 mul2(u64 a, u64 b)
{
    u64 r; asm("mul.rn.f32x2 %0, %1, %2;" : "=l"(r) : "l"(a), "l"(b)); return r;
}
__device__ __forceinline__ u64 add2(u64 a, u64 b)
{
    u64 r; asm("add.rn.f32x2 %0, %1, %2;" : "=l"(r) : "l"(a), "l"(b)); return r;
}
__device__ __forceinline__ void fma2(u64& acc, u64 a, u64 b)
{
    asm("fma.rn.f32x2 %0, %1, %2, %0;" : "+l"(acc) : "l"(a), "l"(b));
}
// split a packed f32 pair into (hi bf16x2 via truncation, lo bf16x2 via rn)
__device__ __forceinline__ void split_pair(u64 v, u32& hi, u32& lo)
{
    u32 l, h;
    asm("mov.b64 {%0, %1}, %2;" : "=r"(l), "=r"(h) : "l"(v));
    asm("prmt.b32 %0, %1, %2, 0x7632;" : "=r"(hi) : "r"(l), "r"(h));
    float fl = __uint_as_float(l);
    float fh = __uint_as_float(h);
    float tl = __uint_as_float(l & 0xFFFF0000u);
    float th = __uint_as_float(h & 0xFFFF0000u);
    float rl = fl - tl;
    float rh = fh - th;
    asm("cvt.rn.bf16x2.f32 %0, %1, %2;" : "=r"(lo) : "f"(rh), "f"(rl));
}

// ---------------------------------------------------------------------------
// Persistent fused kernel: single-accumulator aggregate, conflict-free
// ldmatrix padding, work-stealing, 2 barriers/tile, mma.sync split-2 GEMM
// ---------------------------------------------------------------------------
__global__ void __launch_bounds__(THREADS, 1)
fused_kernel(const ulonglong2* __restrict__ egoq,
             const int*   __restrict__ off,
             const int*   __restrict__ cnt,
             const int2*  __restrict__ meta,
             float*       __restrict__ out)
{
    extern __shared__ char smem[];
    const u32 smem_base = smem_u32_of(smem);
    float* rowsum = (float*)(smem + SM_ROWSUM);   // [2][64]
    int*   ctr    = (int*)(smem + SM_CTR);        // [2]

    const int tid  = threadIdx.x;
    const int lane = tid & 31;
    const int warp = tid >> 5;

    // ---- 0) one-time: load Bhi/Blo into smem (4352 x 16B chunks each)
    {
        const char* shi = (const char*)g_Bhi;
        const char* slo = (const char*)g_Blo;
        #pragma unroll
        for (int i = 0; i < 5; ++i) {
            int m = tid + i * THREADS;
            if (m < 4352) {
                cp_async16(smem_base + SM_B_HI + m * 16, shi + m * 16);
                cp_async16(smem_base + SM_B_LO + m * 16, slo + m * 16);
            }
        }
        asm volatile("cp.async.commit_group;" ::: "memory");
        asm volatile("cp.async.wait_group 0;" ::: "memory");
    }
    if (tid < 2 * BM) rowsum[tid] = 0.f;
    if (tid < 2) ctr[tid] = 0;
    __syncthreads();

    // GEMM constants: warp grid 4m x 8n; warp tile 16m x 16n
    const int m0 = (warp >> 3) * 16;
    const int n0 = (warp & 7) * 16;
    const u32 a_row = m0 + (lane & 15);
    const u32 a_col = (lane >> 4) * 8;
    const u32 aHiBase = smem_base + SM_XHI + a_row * (XP * 2) + a_col * 2;
    const u32 aLoBase = smem_base + SM_XLO + a_row * (XP * 2) + a_col * 2;
    const u32 b_krow = (lane & 7) + ((lane >> 3) & 1) * 8;
    const u32 b_ncol = (lane >> 4) * 8;
    const u32 bHiBase = smem_base + SM_B_HI + b_krow * (BP * 2) + (n0 + b_ncol) * 2;
    const u32 bLoBase = smem_base + SM_B_LO + b_krow * (BP * 2) + (n0 + b_ncol) * 2;
    const int r0 = m0 + (lane >> 2);
    const int r1 = r0 + 8;

    int par = 0;
    for (int tile = blockIdx.x; tile < NBLK; tile += GRID_PERSIST, par ^= 1) {
        const int rowBase = tile * BM;

        // ---- 1) aggregate: S = sum(w*h_src); steal nodes until exhausted
        for (;;) {
            int r;
            if (lane == 0) r = atomicAdd(&ctr[par], 1);
            r = __shfl_sync(0xffffffffu, r, 0);
            if (r >= BM) break;

            int node = rowBase + r;
            bool valid = node < NN;

            ulonglong2 hd2 = valid ? __ldg(egoq + (size_t)node * 32 + lane)
                                   : make_ulonglong2(0ull, 0ull);
            u64 sP0 = 0ull, sP1 = 0ull;

            int n  = valid ? __ldg(cnt + node) : 0;
            int e0 = valid ? __ldg(off + node) : 0;

            for (int c = 0; c < n; c += 32) {
                int lim = min(32, n - c);
                int2 mm = (lane < lim) ? __ldg(meta + e0 + c + lane)
                                       : make_int2(0, 0);
                int nb = lim & ~3;
                ulonglong2 h[4];
                if (nb) {
                    #pragma unroll
                    for (int t = 0; t < 4; ++t) {
                        int s = __shfl_sync(0xffffffffu, mm.x, t);
                        h[t] = __ldg(egoq + (size_t)s * 32 + lane);
                    }
                }
                for (int j = 0; j < nb; j += 4) {
                    u64 w0 = dupf(__int_as_float(__shfl_sync(0xffffffffu, mm.y, j + 0)));
                    u64 w1 = dupf(__int_as_float(__shfl_sync(0xffffffffu, mm.y, j + 1)));
                    u64 w2 = dupf(__int_as_float(__shfl_sync(0xffffffffu, mm.y, j + 2)));
                    u64 w3 = dupf(__int_as_float(__shfl_sync(0xffffffffu, mm.y, j + 3)));
                    ulonglong2 c0 = h[0], c1 = h[1], c2 = h[2], c3 = h[3];
                    if (j + 4 < nb) {
                        #pragma unroll
                        for (int t = 0; t < 4; ++t) {
                            int s = __shfl_sync(0xffffffffu, mm.x, j + 4 + t);
                            h[t] = __ldg(egoq + (size_t)s * 32 + lane);
                        }
                    }
                    fma2(sP0, w0, c0.x); fma2(sP1, w0, c0.y);
                    fma2(sP0, w1, c1.x); fma2(sP1, w1, c1.y);
                    fma2(sP0, w2, c2.x); fma2(sP1, w2, c2.y);
                    fma2(sP0, w3, c3.x); fma2(sP1, w3, c3.y);
                }
                for (int j = nb; j < lim; ++j) {
                    int s0 = __shfl_sync(0xffffffffu, mm.x, j);
                    u64 w0 = dupf(__int_as_float(__shfl_sync(0xffffffffu, mm.y, j)));
                    ulonglong2 h0 = __ldg(egoq + (size_t)s0 * 32 + lane);
                    fma2(sP0, w0, h0.x); fma2(sP1, w0, h0.y);
                }
            }

            // A = ego + S ; Bpart = S .* ego
            u64 aP0 = add2(hd2.x, sP0);
            u64 aP1 = add2(hd2.y, sP1);
            u64 bP0 = mul2(sP0, hd2.x);
            u64 bP1 = mul2(sP1, hd2.y);

            u32 h0, l0, h1, l1, h2, l2, h3, l3;
            split_pair(aP0, h0, l0);
            split_pair(aP1, h1, l1);
            split_pair(bP0, h2, l2);
            split_pair(bP1, h3, l3);

            uint2* xh = (uint2*)(smem + SM_XHI + (size_t)r * (XP * 2));
            uint2* xl = (uint2*)(smem + SM_XLO + (size_t)r * (XP * 2));
            xh[lane]      = make_uint2(h0, h1);
            xh[32 + lane] = make_uint2(h2, h3);
            xl[lane]      = make_uint2(l0, l1);
            xl[32 + lane] = make_uint2(l2, l3);
        }
        __syncthreads();                 // bar1: X complete

        if (tid == 0) ctr[par ^ 1] = 0;
        if (tid < BM) rowsum[(par ^ 1) * BM + tid] = 0.f;

        // ---- 2) GEMM: warp tile 16m x 16n; K=256, split-2
        float acc[2][4];
        #pragma unroll
        for (int i = 0; i < 2; ++i)
            #pragma unroll
            for (int j = 0; j < 4; ++j) acc[i][j] = 0.f;

        #pragma unroll 4
        for (int ks = 0; ks < 16; ++ks) {
            const u32 kOffA = ks * 32;
            const u32 kOffB = ks * 16 * (BP * 2);
            u32 ah0, ah1, ah2, ah3, al0, al1, al2, al3;
            ldsm_x4(ah0, ah1, ah2, ah3, aHiBase + kOffA);
            ldsm_x4(al0, al1, al2, al3, aLoBase + kOffA);

            u32 bh0, bh1, bh2, bh3, bl0, bl1, bl2, bl3;
            ldsm_x4_t(bh0, bh1, bh2, bh3, bHiBase + kOffB);
            ldsm_x4_t(bl0, bl1, bl2, bl3, bLoBase + kOffB);
            mma16816(acc[0], ah0, ah1, ah2, ah3, bh0, bh1);
            mma16816(acc[0], ah0, ah1, ah2, ah3, bl0, bl1);
            mma16816(acc[0], al0, al1, al2, al3, bh0, bh1);
            mma16816(acc[1], ah0, ah1, ah2, ah3, bh2, bh3);
            mma16816(acc[1], ah0, ah1, ah2, ah3, bl2, bl3);
            mma16816(acc[1], al0, al1, al2, al3, bh2, bh3);
        }

        // ---- 3) leaky relu + per-row sumsq partials
        float p0 = 0.f, p1 = 0.f;
        #pragma unroll
        for (int nt = 0; nt < 2; ++nt) {
            #pragma unroll
            for (int j = 0; j < 4; ++j) {
                float v = acc[nt][j];
                v = (v >= 0.f) ? v : 0.2f * v;
                acc[nt][j] = v;
                if (j < 2) p0 = fmaf(v, v, p0);
                else       p1 = fmaf(v, v, p1);
            }
        }
        p0 += __shfl_xor_sync(0xffffffffu, p0, 1);
        p0 += __shfl_xor_sync(0xffffffffu, p0, 2);
        p1 += __shfl_xor_sync(0xffffffffu, p1, 1);
        p1 += __shfl_xor_sync(0xffffffffu, p1, 2);
        if ((lane & 3) == 0) {
            atomicAdd(rowsum + par * BM + r0, p0);
            atomicAdd(rowsum + par * BM + r1, p1);
        }
        __syncthreads();                 // bar2: rowsum complete, X reads done

        // ---- 4) scale + store
        const float inv0 = 1.0f / fmaxf(sqrtf(rowsum[par * BM + r0]), 1e-12f);
        const float inv1 = 1.0f / fmaxf(sqrtf(rowsum[par * BM + r1]), 1e-12f);
        float2* out2 = (float2*)out;
        const int g0 = rowBase + r0;
        const int g1 = rowBase + r1;
        const int colh = (n0 + (lane & 3) * 2) >> 1;
        #pragma unroll
        for (int nt = 0; nt < 2; ++nt) {
            int c2 = colh + nt * 4;
            if (g0 < NN)
                out2[(size_t)g0 * 64 + c2] = make_float2(acc[nt][0] * inv0, acc[nt][1] * inv0);
            if (g1 < NN)
                out2[(size_t)g1 * 64 + c2] = make_float2(acc[nt][2] * inv1, acc[nt][3] * inv1);
        }
    }
}

// ---------------------------------------------------------------------------
// Launch
// ---------------------------------------------------------------------------
extern "C" void kernel_launch(void* const* d_in, const int* in_sizes, int n_in,
                              void* d_out, int out_size)
{
    const float* ego  = (const float*)d_in[0];
    const float* norm = (const float*)d_in[1];
    const int*   src  = (const int*)d_in[2];
    const int*   dst  = (const int*)d_in[3];
    const float* W1   = (const float*)d_in[4];
    const float* W2   = (const float*)d_in[5];
    float* out = (float*)d_out;

    int*  cnt;   cudaGetSymbolAddress((void**)&cnt,   g_cnt);
    int*  off;   cudaGetSymbolAddress((void**)&off,   g_off);
    int*  cur;   cudaGetSymbolAddress((void**)&cur,   g_cur);
    int*  total; cudaGetSymbolAddress((void**)&total, g_total);
    int2* meta;  cudaGetSymbolAddress((void**)&meta,  g_meta);
    __nv_bfloat16* bhi; cudaGetSymbolAddress((void**)&bhi, g_Bhi);
    __nv_bfloat16* blo; cudaGetSymbolAddress((void**)&blo, g_Blo);

    cudaMemsetAsync(cnt, 0, NN * sizeof(int));
    cudaMemsetAsync(total, 0, sizeof(int));
    hist_prep_kernel<<<(EE + 255) / 256, 256>>>(dst, cnt, W1, W2, bhi, blo);
    alloc_kernel<<<(NN + 255) / 256, 256>>>(cnt, off, cur, total);
    scatter_kernel<<<(EE + 255) / 256, 256>>>(src, dst, norm, cur, meta);

    cudaFuncSetAttribute(fused_kernel,
                         cudaFuncAttributeMaxDynamicSharedMemorySize, SM_TOTAL);
    fused_kernel<<<GRID_PERSIST, THREADS, SM_TOTAL>>>(
        (const ulonglong2*)ego, off, cnt, meta, out);
}

// round 15
// speedup vs baseline: 1.5443x; 1.1876x over previous
#include <cuda_runtime.h>
#include <cuda_bf16.h>
#include <cuda_fp16.h>
#include <cstdint>
#include <math.h>

#define NN 100000
#define EE 1000000
#define BM 128
#define THREADS 1024
#define NBLK ((NN + BM - 1) / BM)      // 782
#define GRID_PERSIST 148

// conflict-free strides: odd multiples of 16B
#define BP 136                          // B row: 272 B = 17*16
#define XP 264                          // X row: 528 B = 33*16

#define B_BYTES (256 * BP * 2)          // 69632
#define X_BYTES (BM * XP * 2)           // 67584

// smem byte offsets
#define SM_B      0
#define SM_XHI    (B_BYTES)                     // 69632
#define SM_XLO    (B_BYTES + X_BYTES)           // 137216
#define SM_ROWSUM (B_BYTES + 2 * X_BYTES)       // 204800 (float[2][128])
#define SM_CTR    (SM_ROWSUM + 1024)            // 205824
#define SM_TOTAL  (SM_CTR + 128)                // 205952

typedef unsigned int u32;
typedef unsigned long long u64;

// Scratch
__device__ int  g_cnt[NN];
__device__ int  g_off[NN];
__device__ int  g_cur[NN];
__device__ int  g_total;
__device__ int2 g_meta[EE];
__device__ __align__(16) __half g_Bh[256 * BP];

// ---------------------------------------------------------------------------
// CSR build (hist also performs the B prep so the fused kernel is launch #5)
// ---------------------------------------------------------------------------
__global__ void hist_prep_kernel(const int* __restrict__ dst,
                                 int* __restrict__ cnt,
                                 const float* __restrict__ W1,
                                 const float* __restrict__ W2,
                                 __half* __restrict__ bh)
{
    int e = blockIdx.x * blockDim.x + threadIdx.x;
    if (e < EE) atomicAdd(&cnt[__ldg(dst + e)], 1);
    if (e < 256 * 128) {
        int k = e >> 7;
        int n = e & 127;
        float v = (k < 128) ? __ldg(W1 + k * 128 + n) : __ldg(W2 + (k - 128) * 128 + n);
        bh[k * BP + n] = __float2half_rn(v);
    }
}

__global__ void alloc_kernel(const int* __restrict__ cnt,
                             int* __restrict__ off,
                             int* __restrict__ cur,
                             int* __restrict__ total)
{
    int i = blockIdx.x * blockDim.x + threadIdx.x;
    if (i < NN) {
        int o = atomicAdd(total, cnt[i]);
        off[i] = o;
        cur[i] = o;
    }
}

__global__ void scatter_kernel(const int* __restrict__ src,
                               const int* __restrict__ dst,
                               const float* __restrict__ norm,
                               int* __restrict__ cur,
                               int2* __restrict__ meta)
{
    int e = blockIdx.x * blockDim.x + threadIdx.x;
    if (e >= EE) return;
    int s = __ldg(src + e);
    int d = __ldg(dst + e);
    float w = __ldg(norm + s) * __ldg(norm + d);
    int pos = atomicAdd(&cur[d], 1);
    meta[pos] = make_int2(s, __float_as_int(w));
}

// ---------------------------------------------------------------------------
// PTX helpers
// ---------------------------------------------------------------------------
__device__ __forceinline__ u32 smem_u32_of(const void* p)
{
    u32 a;
    asm("{ .reg .u64 t; cvta.to.shared.u64 t, %1; cvt.u32.u64 %0, t; }"
        : "=r"(a) : "l"(p));
    return a;
}
__device__ __forceinline__ void cp_async16(u32 dst, const void* src)
{
    asm volatile("cp.async.cg.shared.global [%0], [%1], 16;"
                 :: "r"(dst), "l"(src) : "memory");
}
__device__ __forceinline__ void ldsm_x4(u32& r0, u32& r1, u32& r2, u32& r3, u32 addr)
{
    asm volatile("ldmatrix.sync.aligned.m8n8.x4.shared.b16 {%0,%1,%2,%3}, [%4];"
                 : "=r"(r0), "=r"(r1), "=r"(r2), "=r"(r3) : "r"(addr));
}
__device__ __forceinline__ void ldsm_x4_t(u32& r0, u32& r1, u32& r2, u32& r3, u32 addr)
{
    asm volatile("ldmatrix.sync.aligned.m8n8.x4.trans.shared.b16 {%0,%1,%2,%3}, [%4];"
                 : "=r"(r0), "=r"(r1), "=r"(r2), "=r"(r3) : "r"(addr));
}
__device__ __forceinline__ void mma16816(float* c, u32 a0, u32 a1, u32 a2, u32 a3,
                                         u32 b0, u32 b1)
{
    asm volatile(
        "mma.sync.aligned.m16n8k16.row.col.f32.f16.f16.f32 "
        "{%0,%1,%2,%3}, {%4,%5,%6,%7}, {%8,%9}, {%0,%1,%2,%3};"
        : "+f"(c[0]), "+f"(c[1]), "+f"(c[2]), "+f"(c[3])
        : "r"(a0), "r"(a1), "r"(a2), "r"(a3), "r"(b0), "r"(b1));
}
// packed f32x2 helpers
__device__ __forceinline__ u64 dupf(float x)
{
    u64 r; u32 xi = __float_as_uint(x);
    asm("mov.b64 %0, {%1, %1};" : "=l"(r) : "r"(xi));
    return r;
}
__device__ __forceinline__ u64 mul2(u64 a, u64 b)
{
    u64 r; asm("mul.rn.f32x2 %0, %1, %2;" : "=l"(r) : "l"(a), "l"(b)); return r;
}
__device__ __forceinline__ u64 add2(u64 a, u64 b)
{
    u64 r; asm("add.rn.f32x2 %0, %1, %2;" : "=l"(r) : "l"(a), "l"(b)); return r;
}
__device__ __forceinline__ void fma2(u64& acc, u64 a, u64 b)
{
    asm("fma.rn.f32x2 %0, %1, %2, %0;" : "+l"(acc) : "l"(a), "l"(b));
}
// split a packed f32 pair into (hi f16x2 rn, lo f16x2 of residual)
__device__ __forceinline__ void split_pair_f16(u64 v, u32& hi, u32& lo)
{
    u32 l, h;
    asm("mov.b64 {%0, %1}, %2;" : "=r"(l), "=r"(h) : "l"(v));
    float fl = __uint_as_float(l);
    float fh = __uint_as_float(h);
    __half hl = __float2half_rn(fl);
    __half hh = __float2half_rn(fh);
    hi = (u32)__half_as_ushort(hl) | ((u32)__half_as_ushort(hh) << 16);
    float rl = fl - __half2float(hl);
    float rh = fh - __half2float(hh);
    asm("cvt.rn.f16x2.f32 %0, %1, %2;" : "=r"(lo) : "f"(rh), "f"(rl));
}

// ---------------------------------------------------------------------------
// Persistent fused kernel (BM=128): single-accumulator aggregate,
// fp16 X (hi+lo) x fp16 W (single), conflict-free ldmatrix, work-stealing
// ---------------------------------------------------------------------------
__global__ void __launch_bounds__(THREADS, 1)
fused_kernel(const ulonglong2* __restrict__ egoq,
             const int*   __restrict__ off,
             const int*   __restrict__ cnt,
             const int2*  __restrict__ meta,
             float*       __restrict__ out)
{
    extern __shared__ char smem[];
    const u32 smem_base = smem_u32_of(smem);
    float* rowsum = (float*)(smem + SM_ROWSUM);   // [2][128]
    int*   ctr    = (int*)(smem + SM_CTR);        // [2]

    const int tid  = threadIdx.x;
    const int lane = tid & 31;
    const int warp = tid >> 5;

    // ---- 0) one-time: load B (fp16 W) into smem: 4352 x 16B chunks
    {
        const char* sb = (const char*)g_Bh;
        #pragma unroll
        for (int i = 0; i < 5; ++i) {
            int m = tid + i * THREADS;
            if (m < 4352) cp_async16(smem_base + SM_B + m * 16, sb + m * 16);
        }
        asm volatile("cp.async.commit_group;" ::: "memory");
        asm volatile("cp.async.wait_group 0;" ::: "memory");
    }
    if (tid < 2 * BM) rowsum[tid] = 0.f;
    if (tid < 2) ctr[tid] = 0;
    __syncthreads();

    // GEMM constants: warp grid 8m x 4n; warp tile 16m x 32n
    const int m0 = (warp >> 2) * 16;
    const int n0 = (warp & 3) * 32;
    const u32 a_row = m0 + (lane & 15);
    const u32 a_col = (lane >> 4) * 8;
    const u32 aHiBase = smem_base + SM_XHI + a_row * (XP * 2) + a_col * 2;
    const u32 aLoBase = smem_base + SM_XLO + a_row * (XP * 2) + a_col * 2;
    const u32 b_krow = (lane & 7) + ((lane >> 3) & 1) * 8;
    const u32 b_ncol = (lane >> 4) * 8;
    const u32 bBase = smem_base + SM_B + b_krow * (BP * 2) + (n0 + b_ncol) * 2;
    const int r0 = m0 + (lane >> 2);
    const int r1 = r0 + 8;

    int par = 0;
    for (int tile = blockIdx.x; tile < NBLK; tile += GRID_PERSIST, par ^= 1) {
        const int rowBase = tile * BM;

        // ---- 1) aggregate: S = sum(w*h_src); steal nodes until exhausted
        for (;;) {
            int r;
            if (lane == 0) r = atomicAdd(&ctr[par], 1);
            r = __shfl_sync(0xffffffffu, r, 0);
            if (r >= BM) break;

            int node = rowBase + r;
            bool valid = node < NN;

            ulonglong2 hd2 = valid ? __ldg(egoq + (size_t)node * 32 + lane)
                                   : make_ulonglong2(0ull, 0ull);
            u64 sP0 = 0ull, sP1 = 0ull;

            int n  = valid ? __ldg(cnt + node) : 0;
            int e0 = valid ? __ldg(off + node) : 0;

            for (int c = 0; c < n; c += 32) {
                int lim = min(32, n - c);
                int2 mm = (lane < lim) ? __ldg(meta + e0 + c + lane)
                                       : make_int2(0, 0);
                int nb = lim & ~3;
                ulonglong2 h[4];
                if (nb) {
                    #pragma unroll
                    for (int t = 0; t < 4; ++t) {
                        int s = __shfl_sync(0xffffffffu, mm.x, t);
                        h[t] = __ldg(egoq + (size_t)s * 32 + lane);
                    }
                }
                for (int j = 0; j < nb; j += 4) {
                    u64 w0 = dupf(__int_as_float(__shfl_sync(0xffffffffu, mm.y, j + 0)));
                    u64 w1 = dupf(__int_as_float(__shfl_sync(0xffffffffu, mm.y, j + 1)));
                    u64 w2 = dupf(__int_as_float(__shfl_sync(0xffffffffu, mm.y, j + 2)));
                    u64 w3 = dupf(__int_as_float(__shfl_sync(0xffffffffu, mm.y, j + 3)));
                    ulonglong2 c0 = h[0], c1 = h[1], c2 = h[2], c3 = h[3];
                    if (j + 4 < nb) {
                        #pragma unroll
                        for (int t = 0; t < 4; ++t) {
                            int s = __shfl_sync(0xffffffffu, mm.x, j + 4 + t);
                            h[t] = __ldg(egoq + (size_t)s * 32 + lane);
                        }
                    }
                    fma2(sP0, w0, c0.x); fma2(sP1, w0, c0.y);
                    fma2(sP0, w1, c1.x); fma2(sP1, w1, c1.y);
                    fma2(sP0, w2, c2.x); fma2(sP1, w2, c2.y);
                    fma2(sP0, w3, c3.x); fma2(sP1, w3, c3.y);
                }
                for (int j = nb; j < lim; ++j) {
                    int s0 = __shfl_sync(0xffffffffu, mm.x, j);
                    u64 w0 = dupf(__int_as_float(__shfl_sync(0xffffffffu, mm.y, j)));
                    ulonglong2 h0 = __ldg(egoq + (size_t)s0 * 32 + lane);
                    fma2(sP0, w0, h0.x); fma2(sP1, w0, h0.y);
                }
            }

            // A = ego + S ; Bpart = S .* ego
            u64 aP0 = add2(hd2.x, sP0);
            u64 aP1 = add2(hd2.y, sP1);
            u64 bP0 = mul2(sP0, hd2.x);
            u64 bP1 = mul2(sP1, hd2.y);

            u32 h0, l0, h1, l1, h2, l2, h3, l3;
            split_pair_f16(aP0, h0, l0);
            split_pair_f16(aP1, h1, l1);
            split_pair_f16(bP0, h2, l2);
            split_pair_f16(bP1, h3, l3);

            uint2* xh = (uint2*)(smem + SM_XHI + (size_t)r * (XP * 2));
            uint2* xl = (uint2*)(smem + SM_XLO + (size_t)r * (XP * 2));
            xh[lane]      = make_uint2(h0, h1);
            xh[32 + lane] = make_uint2(h2, h3);
            xl[lane]      = make_uint2(l0, l1);
            xl[32 + lane] = make_uint2(l2, l3);
        }
        __syncthreads();                 // bar1: X complete

        if (tid == 0) ctr[par ^ 1] = 0;
        if (tid < BM) rowsum[(par ^ 1) * BM + tid] = 0.f;

        // ---- 2) GEMM: warp tile 16m x 32n; K=256; 2 terms (Xhi+Xlo) x Whi
        float acc[4][4];
        #pragma unroll
        for (int i = 0; i < 4; ++i)
            #pragma unroll
            for (int j = 0; j < 4; ++j) acc[i][j] = 0.f;

        #pragma unroll 4
        for (int ks = 0; ks < 16; ++ks) {
            const u32 kOffA = ks * 32;
            const u32 kOffB = ks * 16 * (BP * 2);
            u32 ah0, ah1, ah2, ah3, al0, al1, al2, al3;
            ldsm_x4(ah0, ah1, ah2, ah3, aHiBase + kOffA);
            ldsm_x4(al0, al1, al2, al3, aLoBase + kOffA);

            u32 b0, b1, b2, b3, b4, b5, b6, b7;
            ldsm_x4_t(b0, b1, b2, b3, bBase + kOffB);
            ldsm_x4_t(b4, b5, b6, b7, bBase + kOffB + 32);
            mma16816(acc[0], ah0, ah1, ah2, ah3, b0, b1);
            mma16816(acc[0], al0, al1, al2, al3, b0, b1);
            mma16816(acc[1], ah0, ah1, ah2, ah3, b2, b3);
            mma16816(acc[1], al0, al1, al2, al3, b2, b3);
            mma16816(acc[2], ah0, ah1, ah2, ah3, b4, b5);
            mma16816(acc[2], al0, al1, al2, al3, b4, b5);
            mma16816(acc[3], ah0, ah1, ah2, ah3, b6, b7);
            mma16816(acc[3], al0, al1, al2, al3, b6, b7);
        }

        // ---- 3) leaky relu + per-row sumsq partials
        float p0 = 0.f, p1 = 0.f;
        #pragma unroll
        for (int nt = 0; nt < 4; ++nt) {
            #pragma unroll
            for (int j = 0; j < 4; ++j) {
                float v = acc[nt][j];
                v = (v >= 0.f) ? v : 0.2f * v;
                acc[nt][j] = v;
                if (j < 2) p0 = fmaf(v, v, p0);
                else       p1 = fmaf(v, v, p1);
            }
        }
        p0 += __shfl_xor_sync(0xffffffffu, p0, 1);
        p0 += __shfl_xor_sync(0xffffffffu, p0, 2);
        p1 += __shfl_xor_sync(0xffffffffu, p1, 1);
        p1 += __shfl_xor_sync(0xffffffffu, p1, 2);
        if ((lane & 3) == 0) {
            atomicAdd(rowsum + par * BM + r0, p0);
            atomicAdd(rowsum + par * BM + r1, p1);
        }
        __syncthreads();                 // bar2: rowsum complete, X reads done

        // ---- 4) scale + store
        const float inv0 = 1.0f / fmaxf(sqrtf(rowsum[par * BM + r0]), 1e-12f);
        const float inv1 = 1.0f / fmaxf(sqrtf(rowsum[par * BM + r1]), 1e-12f);
        float2* out2 = (float2*)out;
        const int g0 = rowBase + r0;
        const int g1 = rowBase + r1;
        const int colh = (n0 + (lane & 3) * 2) >> 1;
        #pragma unroll
        for (int nt = 0; nt < 4; ++nt) {
            int c2 = colh + nt * 4;
            if (g0 < NN)
                out2[(size_t)g0 * 64 + c2] = make_float2(acc[nt][0] * inv0, acc[nt][1] * inv0);
            if (g1 < NN)
                out2[(size_t)g1 * 64 + c2] = make_float2(acc[nt][2] * inv1, acc[nt][3] * inv1);
        }
    }
}

// ---------------------------------------------------------------------------
// Launch
// ---------------------------------------------------------------------------
extern "C" void kernel_launch(void* const* d_in, const int* in_sizes, int n_in,
                              void* d_out, int out_size)
{
    const float* ego  = (const float*)d_in[0];
    const float* norm = (const float*)d_in[1];
    const int*   src  = (const int*)d_in[2];
    const int*   dst  = (const int*)d_in[3];
    const float* W1   = (const float*)d_in[4];
    const float* W2   = (const float*)d_in[5];
    float* out = (float*)d_out;

    int*  cnt;   cudaGetSymbolAddress((void**)&cnt,   g_cnt);
    int*  off;   cudaGetSymbolAddress((void**)&off,   g_off);
    int*  cur;   cudaGetSymbolAddress((void**)&cur,   g_cur);
    int*  total; cudaGetSymbolAddress((void**)&total, g_total);
    int2* meta;  cudaGetSymbolAddress((void**)&meta,  g_meta);
    __half* bh;  cudaGetSymbolAddress((void**)&bh,    g_Bh);

    cudaMemsetAsync(cnt, 0, NN * sizeof(int));
    cudaMemsetAsync(total, 0, sizeof(int));
    hist_prep_kernel<<<(EE + 255) / 256, 256>>>(dst, cnt, W1, W2, bh);
    alloc_kernel<<<(NN + 255) / 256, 256>>>(cnt, off, cur, total);
    scatter_kernel<<<(EE + 255) / 256, 256>>>(src, dst, norm, cur, meta);

    cudaFuncSetAttribute(fused_kernel,
                         cudaFuncAttributeMaxDynamicSharedMemorySize, SM_TOTAL);
    fused_kernel<<<GRID_PERSIST, THREADS, SM_TOTAL>>>(
        (const ulonglong2*)ego, off, cnt, meta, out);
}

// round 16
// speedup vs baseline: 1.7144x; 1.1101x over previous
#include <cuda_runtime.h>
#include <cuda_bf16.h>
#include <cuda_fp16.h>
#include <cstdint>
#include <math.h>

#define NN 100000
#define EE 1000000
#define BM 128
#define THREADS 1024
#define NBLK ((NN + BM - 1) / BM)      // 782
#define GRID_PERSIST 148

// conflict-free strides: odd multiples of 16B
#define BP 136                          // B row: 272 B = 17*16
#define XP 264                          // X row: 528 B = 33*16

#define B_BYTES (256 * BP * 2)          // 69632
#define X_BYTES (BM * XP * 2)           // 67584

// smem byte offsets
#define SM_B      0
#define SM_XHI    (B_BYTES)                     // 69632
#define SM_ROWSUM (B_BYTES + X_BYTES)           // 137216 (float[2][128])
#define SM_CTR    (SM_ROWSUM + 1024)            // 138240
#define SM_TOTAL  (SM_CTR + 128)                // 138368

typedef unsigned int u32;
typedef unsigned long long u64;

// Scratch
__device__ int  g_cnt[NN];
__device__ int  g_off[NN];
__device__ int  g_cur[NN];
__device__ int  g_total;
__device__ int2 g_meta[EE];
__device__ __align__(16) __half g_Bh[256 * BP];

// ---------------------------------------------------------------------------
// CSR build (hist also performs the B prep so the fused kernel is launch #5)
// ---------------------------------------------------------------------------
__global__ void hist_prep_kernel(const int* __restrict__ dst,
                                 int* __restrict__ cnt,
                                 const float* __restrict__ W1,
                                 const float* __restrict__ W2,
                                 __half* __restrict__ bh)
{
    int e = blockIdx.x * blockDim.x + threadIdx.x;
    if (e < EE) atomicAdd(&cnt[__ldg(dst + e)], 1);
    if (e < 256 * 128) {
        int k = e >> 7;
        int n = e & 127;
        float v = (k < 128) ? __ldg(W1 + k * 128 + n) : __ldg(W2 + (k - 128) * 128 + n);
        bh[k * BP + n] = __float2half_rn(v);
    }
}

__global__ void alloc_kernel(const int* __restrict__ cnt,
                             int* __restrict__ off,
                             int* __restrict__ cur,
                             int* __restrict__ total)
{
    int i = blockIdx.x * blockDim.x + threadIdx.x;
    if (i < NN) {
        int o = atomicAdd(total, cnt[i]);
        off[i] = o;
        cur[i] = o;
    }
}

__global__ void scatter_kernel(const int* __restrict__ src,
                               const int* __restrict__ dst,
                               const float* __restrict__ norm,
                               int* __restrict__ cur,
                               int2* __restrict__ meta)
{
    int e = blockIdx.x * blockDim.x + threadIdx.x;
    if (e >= EE) return;
    int s = __ldg(src + e);
    int d = __ldg(dst + e);
    float w = __ldg(norm + s) * __ldg(norm + d);
    int pos = atomicAdd(&cur[d], 1);
    meta[pos] = make_int2(s, __float_as_int(w));
}

// ---------------------------------------------------------------------------
// PTX helpers
// ---------------------------------------------------------------------------
__device__ __forceinline__ u32 smem_u32_of(const void* p)
{
    u32 a;
    asm("{ .reg .u64 t; cvta.to.shared.u64 t, %1; cvt.u32.u64 %0, t; }"
        : "=r"(a) : "l"(p));
    return a;
}
__device__ __forceinline__ void cp_async16(u32 dst, const void* src)
{
    asm volatile("cp.async.cg.shared.global [%0], [%1], 16;"
                 :: "r"(dst), "l"(src) : "memory");
}
__device__ __forceinline__ void ldsm_x4(u32& r0, u32& r1, u32& r2, u32& r3, u32 addr)
{
    asm volatile("ldmatrix.sync.aligned.m8n8.x4.shared.b16 {%0,%1,%2,%3}, [%4];"
                 : "=r"(r0), "=r"(r1), "=r"(r2), "=r"(r3) : "r"(addr));
}
__device__ __forceinline__ void ldsm_x4_t(u32& r0, u32& r1, u32& r2, u32& r3, u32 addr)
{
    asm volatile("ldmatrix.sync.aligned.m8n8.x4.trans.shared.b16 {%0,%1,%2,%3}, [%4];"
                 : "=r"(r0), "=r"(r1), "=r"(r2), "=r"(r3) : "r"(addr));
}
__device__ __forceinline__ void mma16816(float* c, u32 a0, u32 a1, u32 a2, u32 a3,
                                         u32 b0, u32 b1)
{
    asm volatile(
        "mma.sync.aligned.m16n8k16.row.col.f32.f16.f16.f32 "
        "{%0,%1,%2,%3}, {%4,%5,%6,%7}, {%8,%9}, {%0,%1,%2,%3};"
        : "+f"(c[0]), "+f"(c[1]), "+f"(c[2]), "+f"(c[3])
        : "r"(a0), "r"(a1), "r"(a2), "r"(a3), "r"(b0), "r"(b1));
}
// packed f32x2 helpers
__device__ __forceinline__ u64 dupf(float x)
{
    u64 r; u32 xi = __float_as_uint(x);
    asm("mov.b64 %0, {%1, %1};" : "=l"(r) : "r"(xi));
    return r;
}
__device__ __forceinline__ u64 mul2(u64 a, u64 b)
{
    u64 r; asm("mul.rn.f32x2 %0, %1, %2;" : "=l"(r) : "l"(a), "l"(b)); return r;
}
__device__ __forceinline__ u64 add2(u64 a, u64 b)
{
    u64 r; asm("add.rn.f32x2 %0, %1, %2;" : "=l"(r) : "l"(a), "l"(b)); return r;
}
__device__ __forceinline__ void fma2(u64& acc, u64 a, u64 b)
{
    asm("fma.rn.f32x2 %0, %1, %2, %0;" : "+l"(acc) : "l"(a), "l"(b));
}
// convert a packed f32 pair to one f16x2 (rn)
__device__ __forceinline__ u32 pack_f16(u64 v)
{
    u32 l, h, r;
    asm("mov.b64 {%0, %1}, %2;" : "=r"(l), "=r"(h) : "l"(v));
    asm("cvt.rn.f16x2.f32 %0, %1, %2;"
        : "=r"(r) : "f"(__uint_as_float(h)), "f"(__uint_as_float(l)));
    return r;
}

// ---------------------------------------------------------------------------
// Persistent fused kernel (BM=128): single-accumulator aggregate,
// fp16 X (single) x fp16 W (single), conflict-free ldmatrix, work-stealing
// ---------------------------------------------------------------------------
__global__ void __launch_bounds__(THREADS, 1)
fused_kernel(const ulonglong2* __restrict__ egoq,
             const int*   __restrict__ off,
             const int*   __restrict__ cnt,
             const int2*  __restrict__ meta,
             float*       __restrict__ out)
{
    extern __shared__ char smem[];
    const u32 smem_base = smem_u32_of(smem);
    float* rowsum = (float*)(smem + SM_ROWSUM);   // [2][128]
    int*   ctr    = (int*)(smem + SM_CTR);        // [2]

    const int tid  = threadIdx.x;
    const int lane = tid & 31;
    const int warp = tid >> 5;

    // ---- 0) one-time: load B (fp16 W) into smem: 4352 x 16B chunks
    {
        const char* sb = (const char*)g_Bh;
        #pragma unroll
        for (int i = 0; i < 5; ++i) {
            int m = tid + i * THREADS;
            if (m < 4352) cp_async16(smem_base + SM_B + m * 16, sb + m * 16);
        }
        asm volatile("cp.async.commit_group;" ::: "memory");
        asm volatile("cp.async.wait_group 0;" ::: "memory");
    }
    if (tid < 2 * BM) rowsum[tid] = 0.f;
    if (tid < 2) ctr[tid] = 0;
    __syncthreads();

    // GEMM constants: warp grid 8m x 4n; warp tile 16m x 32n
    const int m0 = (warp >> 2) * 16;
    const int n0 = (warp & 3) * 32;
    const u32 a_row = m0 + (lane & 15);
    const u32 a_col = (lane >> 4) * 8;
    const u32 aBase = smem_base + SM_XHI + a_row * (XP * 2) + a_col * 2;
    const u32 b_krow = (lane & 7) + ((lane >> 3) & 1) * 8;
    const u32 b_ncol = (lane >> 4) * 8;
    const u32 bBase = smem_base + SM_B + b_krow * (BP * 2) + (n0 + b_ncol) * 2;
    const int r0 = m0 + (lane >> 2);
    const int r1 = r0 + 8;

    int par = 0;
    for (int tile = blockIdx.x; tile < NBLK; tile += GRID_PERSIST, par ^= 1) {
        const int rowBase = tile * BM;

        // ---- 1) aggregate: S = sum(w*h_src); steal nodes until exhausted
        for (;;) {
            int r;
            if (lane == 0) r = atomicAdd(&ctr[par], 1);
            r = __shfl_sync(0xffffffffu, r, 0);
            if (r >= BM) break;

            int node = rowBase + r;
            bool valid = node < NN;

            ulonglong2 hd2 = valid ? __ldg(egoq + (size_t)node * 32 + lane)
                                   : make_ulonglong2(0ull, 0ull);
            u64 sP0 = 0ull, sP1 = 0ull;

            int n  = valid ? __ldg(cnt + node) : 0;
            int e0 = valid ? __ldg(off + node) : 0;

            for (int c = 0; c < n; c += 32) {
                int lim = min(32, n - c);
                int2 mm = (lane < lim) ? __ldg(meta + e0 + c + lane)
                                       : make_int2(0, 0);
                int nb = lim & ~3;
                ulonglong2 h[4];
                if (nb) {
                    #pragma unroll
                    for (int t = 0; t < 4; ++t) {
                        int s = __shfl_sync(0xffffffffu, mm.x, t);
                        h[t] = __ldg(egoq + (size_t)s * 32 + lane);
                    }
                }
                for (int j = 0; j < nb; j += 4) {
                    u64 w0 = dupf(__int_as_float(__shfl_sync(0xffffffffu, mm.y, j + 0)));
                    u64 w1 = dupf(__int_as_float(__shfl_sync(0xffffffffu, mm.y, j + 1)));
                    u64 w2 = dupf(__int_as_float(__shfl_sync(0xffffffffu, mm.y, j + 2)));
                    u64 w3 = dupf(__int_as_float(__shfl_sync(0xffffffffu, mm.y, j + 3)));
                    ulonglong2 c0 = h[0], c1 = h[1], c2 = h[2], c3 = h[3];
                    if (j + 4 < nb) {
                        #pragma unroll
                        for (int t = 0; t < 4; ++t) {
                            int s = __shfl_sync(0xffffffffu, mm.x, j + 4 + t);
                            h[t] = __ldg(egoq + (size_t)s * 32 + lane);
                        }
                    }
                    fma2(sP0, w0, c0.x); fma2(sP1, w0, c0.y);
                    fma2(sP0, w1, c1.x); fma2(sP1, w1, c1.y);
                    fma2(sP0, w2, c2.x); fma2(sP1, w2, c2.y);
                    fma2(sP0, w3, c3.x); fma2(sP1, w3, c3.y);
                }
                for (int j = nb; j < lim; ++j) {
                    int s0 = __shfl_sync(0xffffffffu, mm.x, j);
                    u64 w0 = dupf(__int_as_float(__shfl_sync(0xffffffffu, mm.y, j)));
                    ulonglong2 h0 = __ldg(egoq + (size_t)s0 * 32 + lane);
                    fma2(sP0, w0, h0.x); fma2(sP1, w0, h0.y);
                }
            }

            // A = ego + S ; Bpart = S .* ego
            u64 aP0 = add2(hd2.x, sP0);
            u64 aP1 = add2(hd2.y, sP1);
            u64 bP0 = mul2(sP0, hd2.x);
            u64 bP1 = mul2(sP1, hd2.y);

            uint4 xv;
            xv.x = pack_f16(aP0);
            xv.y = pack_f16(aP1);
            xv.z = pack_f16(bP0);
            xv.w = pack_f16(bP1);

            // row r: halves: [A (128 k) | B (128 k)] as f16
            uint2* xh = (uint2*)(smem + SM_XHI + (size_t)r * (XP * 2));
            xh[lane]      = make_uint2(xv.x, xv.y);
            xh[32 + lane] = make_uint2(xv.z, xv.w);
        }
        __syncthreads();                 // bar1: X complete

        if (tid == 0) ctr[par ^ 1] = 0;
        if (tid < BM) rowsum[(par ^ 1) * BM + tid] = 0.f;

        // ---- 2) GEMM: warp tile 16m x 32n; K=256; single term
        float acc[4][4];
        #pragma unroll
        for (int i = 0; i < 4; ++i)
            #pragma unroll
            for (int j = 0; j < 4; ++j) acc[i][j] = 0.f;

        #pragma unroll 4
        for (int ks = 0; ks < 16; ++ks) {
            const u32 kOffA = ks * 32;
            const u32 kOffB = ks * 16 * (BP * 2);
            u32 a0, a1, a2, a3;
            ldsm_x4(a0, a1, a2, a3, aBase + kOffA);

            u32 b0, b1, b2, b3, b4, b5, b6, b7;
            ldsm_x4_t(b0, b1, b2, b3, bBase + kOffB);
            ldsm_x4_t(b4, b5, b6, b7, bBase + kOffB + 32);
            mma16816(acc[0], a0, a1, a2, a3, b0, b1);
            mma16816(acc[1], a0, a1, a2, a3, b2, b3);
            mma16816(acc[2], a0, a1, a2, a3, b4, b5);
            mma16816(acc[3], a0, a1, a2, a3, b6, b7);
        }

        // ---- 3) leaky relu + per-row sumsq partials
        float p0 = 0.f, p1 = 0.f;
        #pragma unroll
        for (int nt = 0; nt < 4; ++nt) {
            #pragma unroll
            for (int j = 0; j < 4; ++j) {
                float v = acc[nt][j];
                v = (v >= 0.f) ? v : 0.2f * v;
                acc[nt][j] = v;
                if (j < 2) p0 = fmaf(v, v, p0);
                else       p1 = fmaf(v, v, p1);
            }
        }
        p0 += __shfl_xor_sync(0xffffffffu, p0, 1);
        p0 += __shfl_xor_sync(0xffffffffu, p0, 2);
        p1 += __shfl_xor_sync(0xffffffffu, p1, 1);
        p1 += __shfl_xor_sync(0xffffffffu, p1, 2);
        if ((lane & 3) == 0) {
            atomicAdd(rowsum + par * BM + r0, p0);
            atomicAdd(rowsum + par * BM + r1, p1);
        }
        __syncthreads();                 // bar2: rowsum complete, X reads done

        // ---- 4) scale + store
        const float inv0 = 1.0f / fmaxf(sqrtf(rowsum[par * BM + r0]), 1e-12f);
        const float inv1 = 1.0f / fmaxf(sqrtf(rowsum[par * BM + r1]), 1e-12f);
        float2* out2 = (float2*)out;
        const int g0 = rowBase + r0;
        const int g1 = rowBase + r1;
        const int colh = (n0 + (lane & 3) * 2) >> 1;
        #pragma unroll
        for (int nt = 0; nt < 4; ++nt) {
            int c2 = colh + nt * 4;
            if (g0 < NN)
                out2[(size_t)g0 * 64 + c2] = make_float2(acc[nt][0] * inv0, acc[nt][1] * inv0);
            if (g1 < NN)
                out2[(size_t)g1 * 64 + c2] = make_float2(acc[nt][2] * inv1, acc[nt][3] * inv1);
        }
    }
}

// ---------------------------------------------------------------------------
// Launch
// ---------------------------------------------------------------------------
extern "C" void kernel_launch(void* const* d_in, const int* in_sizes, int n_in,
                              void* d_out, int out_size)
{
    const float* ego  = (const float*)d_in[0];
    const float* norm = (const float*)d_in[1];
    const int*   src  = (const int*)d_in[2];
    const int*   dst  = (const int*)d_in[3];
    const float* W1   = (const float*)d_in[4];
    const float* W2   = (const float*)d_in[5];
    float* out = (float*)d_out;

    int*  cnt;   cudaGetSymbolAddress((void**)&cnt,   g_cnt);
    int*  off;   cudaGetSymbolAddress((void**)&off,   g_off);
    int*  cur;   cudaGetSymbolAddress((void**)&cur,   g_cur);
    int*  total; cudaGetSymbolAddress((void**)&total, g_total);
    int2* meta;  cudaGetSymbolAddress((void**)&meta,  g_meta);
    __half* bh;  cudaGetSymbolAddress((void**)&bh,    g_Bh);

    cudaMemsetAsync(cnt, 0, NN * sizeof(int));
    cudaMemsetAsync(total, 0, sizeof(int));
    hist_prep_kernel<<<(EE + 255) / 256, 256>>>(dst, cnt, W1, W2, bh);
    alloc_kernel<<<(NN + 255) / 256, 256>>>(cnt, off, cur, total);
    scatter_kernel<<<(EE + 255) / 256, 256>>>(src, dst, norm, cur, meta);

    cudaFuncSetAttribute(fused_kernel,
                         cudaFuncAttributeMaxDynamicSharedMemorySize, SM_TOTAL);
    fused_kernel<<<GRID_PERSIST, THREADS, SM_TOTAL>>>(
        (const ulonglong2*)ego, off, cnt, meta, out);
}